// round 7
// baseline (speedup 1.0000x reference)
#include <cuda_runtime.h>

#define BATCH   65536
#define NPLAYER 3
#define OBSD    48
#define TB      32
#define THREADS 512

// pitches (floats)
#define PHID 388
#define PENC 580
#define PH1  260
#define PSCR 260

// smem float offsets
#define HID_OFF 0
#define ENC_OFF 12416
#define H1_OFF  (ENC_OFF + 18560)
#define W3_OFF  (H1_OFF + 8320)
#define SMEM_FLOATS (W3_OFF + 772)

// packed weight buffer: per player 67072 float4s
//   enc (3 passes x 4608) : [0, 13824)
//   pi1 (16w x 36c x 2jp x 32) : [13824, 50688)
//   pi2 (16w x 16c x 2jp x 32) : [50688, 67072)
#define PK_PLAYER 67072
#define PK_TOTAL  (3 * PK_PLAYER)   // 201216 float4 = 3.2MB
#define PK_PI1    13824
#define PK_PI2    50688

__device__ float4 g_pk4[PK_TOTAL];

__device__ __forceinline__ float lrelu(float x) { return fmaxf(x, 0.01f * x); }

__device__ __forceinline__ unsigned f2tf(float x) {
    unsigned r;
    asm("cvt.rna.tf32.f32 %0, %1;" : "=r"(r) : "f"(x));
    return r;
}
__device__ __forceinline__ float tf32f(float x) { return __uint_as_float(f2tf(x)); }

__device__ __forceinline__ void mma_tf32(float d[4], unsigned a0, unsigned a1,
                                         unsigned a2, unsigned a3,
                                         unsigned b0, unsigned b1) {
    asm volatile(
        "mma.sync.aligned.m16n8k8.row.col.f32.tf32.tf32.f32 "
        "{%0,%1,%2,%3}, {%4,%5,%6,%7}, {%8,%9}, {%0,%1,%2,%3};"
        : "+f"(d[0]), "+f"(d[1]), "+f"(d[2]), "+f"(d[3])
        : "r"(a0), "r"(a1), "r"(a2), "r"(a3), "r"(b0), "r"(b1));
}

// =================== repack kernel: fragment-order, tf32-converted ===================
__global__ void repack_kernel(const float* __restrict__ prop_W2,
                              const float* __restrict__ ext_W2,
                              const float* __restrict__ opp_W2,
                              const float* __restrict__ pi_W1,
                              const float* __restrict__ pi_W2) {
    int idx = blockIdx.x * 256 + threadIdx.x;
    if (idx >= PK_TOTAL) return;
    int p = idx / PK_PLAYER;
    int r = idx - p * PK_PLAYER;
    float o[4];
    if (r < PK_PI1) {
        // enc packed: (((warp*3+tp)*4+k8)*32+lane) per pass
        int pp = r / 4608, e = r - pp * 4608;
        int warp = e / 384, rem = e - warp * 384;
        int tp = rem >> 7, rem2 = rem & 127;
        int k8 = rem2 >> 5, lane = rem2 & 31;
        int gr = lane >> 2, gc = lane & 3;
        #pragma unroll
        for (int q = 0; q < 4; q++) {
            int t = tp * 2 + (q >> 1), b = q & 1;
            int c0 = warp * 48 + t * 8;
            int k = k8 * 8 + gc + b * 4;
            float s;
            if (pp == 0) {
                int head = c0 >> 6;
                s = prop_W2[((size_t)(p * 9 + head) * 32 + k) * 64 + (c0 & 63) + gr];
            } else if (pp == 1) {
                int head = (c0 >= 288) ? 1 : 0;
                s = ext_W2[((size_t)(p * 2 + head) * 32 + k) * 288 + c0 - head * 288 + gr];
            } else {
                s = opp_W2[((size_t)p * 32 + k) * 576 + c0 + gr];
            }
            o[q] = tf32f(s);
        }
    } else if (r < PK_PI2) {
        int e = r - PK_PI1;
        int w = e / 2304, rem = e - w * 2304;       // 36c x 2jp x 32
        int c = rem >> 6, rem2 = rem & 63;
        int jp = rem2 >> 5, lane = rem2 & 31;
        int h = w >> 3, nw = w & 7, gr = lane >> 2, gc = lane & 3;
        #pragma unroll
        for (int q = 0; q < 4; q++) {
            int j = jp * 2 + (q >> 1), b = q & 1;
            int k = h * 288 + c * 8 + gc + b * 4;
            int n = nw * 32 + j * 8 + gr;
            o[q] = tf32f(pi_W1[(size_t)p * 147456 + k * 256 + n]);
        }
    } else {
        int e = r - PK_PI2;
        int w = e >> 10, rem = e & 1023;            // 16c x 2jp x 32
        int c = rem >> 6, rem2 = rem & 63;
        int jp = rem2 >> 5, lane = rem2 & 31;
        int h = w >> 3, nw = w & 7, gr = lane >> 2, gc = lane & 3;
        #pragma unroll
        for (int q = 0; q < 4; q++) {
            int j = jp * 2 + (q >> 1), b = q & 1;
            int k = h * 128 + c * 8 + gc + b * 4;
            int n = nw * 32 + j * 8 + gr;
            o[q] = tf32f(pi_W2[(size_t)p * 65536 + k * 256 + n]);
        }
    }
    g_pk4[idx] = make_float4(o[0], o[1], o[2], o[3]);
}

// =================== stage-1b pass: packed B, no syncs ===================
// MODE 0: store, 1: accumulate, 2: accumulate + tf32-finalize
template<int HC, int NH, int ABASE, int MODE, int PPIDX>
__device__ __forceinline__ void enc_pass(const float* __restrict__ bias,
                                         const float* s_hid, float* s_enc,
                                         int warp, int lane, int p) {
    if (warp >= 12) return;
    const int gr = lane >> 2, gc = lane & 3;
    const int cw = warp * 48;
    const float4* pk = g_pk4 + (size_t)p * PK_PLAYER + PPIDX * 4608 + warp * 384 + lane;

    int headA[6];
    #pragma unroll
    for (int t = 0; t < 6; t++) {
        int c0 = cw + t * 8;
        headA[t] = (HC == 576) ? 0 : ((HC == 64) ? (c0 >> 6) : (c0 >= 288 ? 1 : 0));
    }

    float acc[6][2][4];
    #pragma unroll
    for (int t = 0; t < 6; t++)
        #pragma unroll
        for (int m = 0; m < 2; m++)
            #pragma unroll
            for (int u = 0; u < 4; u++) acc[t][m][u] = 0.f;

    #pragma unroll
    for (int k8 = 0; k8 < 4; k8++) {
        float4 bv[3];
        #pragma unroll
        for (int tp = 0; tp < 3; tp++) bv[tp] = pk[(tp * 4 + k8) * 32];
        int cur = -1;
        unsigned a[2][4];
        #pragma unroll
        for (int t = 0; t < 6; t++) {
            if (headA[t] != cur) {
                cur = headA[t];
                int ac = ABASE + cur * 32 + k8 * 8 + gc;
                #pragma unroll
                for (int m = 0; m < 2; m++) {
                    int r = m * 16 + gr;
                    a[m][0] = __float_as_uint(s_hid[(r    ) * PHID + ac    ]);
                    a[m][1] = __float_as_uint(s_hid[(r + 8) * PHID + ac    ]);
                    a[m][2] = __float_as_uint(s_hid[(r    ) * PHID + ac + 4]);
                    a[m][3] = __float_as_uint(s_hid[(r + 8) * PHID + ac + 4]);
                }
            }
            unsigned b0 = __float_as_uint((t & 1) ? bv[t >> 1].z : bv[t >> 1].x);
            unsigned b1 = __float_as_uint((t & 1) ? bv[t >> 1].w : bv[t >> 1].y);
            mma_tf32(acc[t][0], a[0][0], a[0][1], a[0][2], a[0][3], b0, b1);
            mma_tf32(acc[t][1], a[1][0], a[1][1], a[1][2], a[1][3], b0, b1);
        }
    }

    #pragma unroll
    for (int t = 0; t < 6; t++) {
        int cb = cw + t * 8 + 2 * gc;
        int head = headA[t];
        int cc = cb - head * HC;
        float b0 = bias[(p * NH + head) * HC + cc];
        float b1 = bias[(p * NH + head) * HC + cc + 1];
        #pragma unroll
        for (int m = 0; m < 2; m++) {
            int r = m * 16 + gr;
            float v00 = lrelu(acc[t][m][0] + b0), v01 = lrelu(acc[t][m][1] + b1);
            float v10 = lrelu(acc[t][m][2] + b0), v11 = lrelu(acc[t][m][3] + b1);
            float* e0 = &s_enc[(r    ) * PENC + cb];
            float* e1 = &s_enc[(r + 8) * PENC + cb];
            if (MODE == 0)      { e0[0] = v00; e0[1] = v01; e1[0] = v10; e1[1] = v11; }
            else if (MODE == 1) { e0[0] += v00; e0[1] += v01; e1[0] += v10; e1[1] += v11; }
            else {
                e0[0] = tf32f(e0[0] + v00); e0[1] = tf32f(e0[1] + v01);
                e1[0] = tf32f(e1[0] + v10); e1[1] = tf32f(e1[1] + v11);
            }
        }
    }
}

// =================== pi-head GEMM: packed B, K-split halves ===================
template<int KHALF, int NC, int PKOFF, int PA, bool OUT_TF32>
__device__ __forceinline__ void pi_stage(const float* __restrict__ bias,
                                         const float* sA, float* scr,
                                         float* outp, int outPitch,
                                         int warp, int lane, int p) {
    const int h = warp >> 3, nw = warp & 7, n0 = nw * 32;
    const int gr = lane >> 2, gc = lane & 3;
    const int kbase = h * KHALF + gc;
    const float4* pk = g_pk4 + (size_t)p * PK_PLAYER + PKOFF
                     + (size_t)(h * 8 + nw) * NC * 64 + lane;

    float acc[4][2][4];
    #pragma unroll
    for (int j = 0; j < 4; j++)
        #pragma unroll
        for (int m = 0; m < 2; m++)
            #pragma unroll
            for (int u = 0; u < 4; u++) acc[j][m][u] = 0.f;

    #pragma unroll 2
    for (int c = 0; c < NC; c++) {
        float4 v0 = pk[(c * 2    ) * 32];
        float4 v1 = pk[(c * 2 + 1) * 32];
        const int kg = kbase + c * 8;
        unsigned a[2][4];
        #pragma unroll
        for (int m = 0; m < 2; m++) {
            int r = m * 16 + gr;
            a[m][0] = __float_as_uint(sA[(r    ) * PA + kg    ]);
            a[m][1] = __float_as_uint(sA[(r + 8) * PA + kg    ]);
            a[m][2] = __float_as_uint(sA[(r    ) * PA + kg + 4]);
            a[m][3] = __float_as_uint(sA[(r + 8) * PA + kg + 4]);
        }
        mma_tf32(acc[0][0], a[0][0], a[0][1], a[0][2], a[0][3],
                 __float_as_uint(v0.x), __float_as_uint(v0.y));
        mma_tf32(acc[0][1], a[1][0], a[1][1], a[1][2], a[1][3],
                 __float_as_uint(v0.x), __float_as_uint(v0.y));
        mma_tf32(acc[1][0], a[0][0], a[0][1], a[0][2], a[0][3],
                 __float_as_uint(v0.z), __float_as_uint(v0.w));
        mma_tf32(acc[1][1], a[1][0], a[1][1], a[1][2], a[1][3],
                 __float_as_uint(v0.z), __float_as_uint(v0.w));
        mma_tf32(acc[2][0], a[0][0], a[0][1], a[0][2], a[0][3],
                 __float_as_uint(v1.x), __float_as_uint(v1.y));
        mma_tf32(acc[2][1], a[1][0], a[1][1], a[1][2], a[1][3],
                 __float_as_uint(v1.x), __float_as_uint(v1.y));
        mma_tf32(acc[3][0], a[0][0], a[0][1], a[0][2], a[0][3],
                 __float_as_uint(v1.z), __float_as_uint(v1.w));
        mma_tf32(acc[3][1], a[1][0], a[1][1], a[1][2], a[1][3],
                 __float_as_uint(v1.z), __float_as_uint(v1.w));
    }

    // K-split reduction
    if (h == 1) {
        #pragma unroll
        for (int j = 0; j < 4; j++) {
            int cA = n0 + j * 8 + 2 * gc;
            #pragma unroll
            for (int m = 0; m < 2; m++) {
                int r = m * 16 + gr;
                scr[(r    ) * PSCR + cA] = acc[j][m][0]; scr[(r    ) * PSCR + cA + 1] = acc[j][m][1];
                scr[(r + 8) * PSCR + cA] = acc[j][m][2]; scr[(r + 8) * PSCR + cA + 1] = acc[j][m][3];
            }
        }
    }
    __syncthreads();
    if (h == 0) {
        #pragma unroll
        for (int j = 0; j < 4; j++) {
            int cA = n0 + j * 8 + 2 * gc;
            float b0 = bias[cA], b1 = bias[cA + 1];
            #pragma unroll
            for (int m = 0; m < 2; m++) {
                int r = m * 16 + gr;
                float v00 = lrelu(acc[j][m][0] + scr[(r    ) * PSCR + cA    ] + b0);
                float v01 = lrelu(acc[j][m][1] + scr[(r    ) * PSCR + cA + 1] + b1);
                float v10 = lrelu(acc[j][m][2] + scr[(r + 8) * PSCR + cA    ] + b0);
                float v11 = lrelu(acc[j][m][3] + scr[(r + 8) * PSCR + cA + 1] + b1);
                if (OUT_TF32) { v00 = tf32f(v00); v01 = tf32f(v01); v10 = tf32f(v10); v11 = tf32f(v11); }
                outp[(r    ) * outPitch + cA    ] = v00;
                outp[(r    ) * outPitch + cA + 1] = v01;
                outp[(r + 8) * outPitch + cA    ] = v10;
                outp[(r + 8) * outPitch + cA + 1] = v11;
            }
        }
    }
}

__global__ __launch_bounds__(THREADS, 1)
void mlpac_kernel(
    const float* __restrict__ obs,
    const float* __restrict__ prop_W1, const float* __restrict__ prop_b1,
    const float* __restrict__ prop_b2,
    const float* __restrict__ ext_W1,  const float* __restrict__ ext_b1,
    const float* __restrict__ ext_b2,
    const float* __restrict__ opp_W1,  const float* __restrict__ opp_b1,
    const float* __restrict__ opp_b2,
    const float* __restrict__ pi_b1,   const float* __restrict__ pi_b2,
    const float* __restrict__ pi_W3,   const float* __restrict__ pi_b3,
    float* __restrict__ out)
{
    extern __shared__ float sm[];
    float* s_hid  = sm + HID_OFF;
    float* s_enc  = sm + ENC_OFF;
    float* s_h1   = sm + H1_OFF;
    float* s_obs  = s_enc;
    float* s_w3   = sm + W3_OFF;
    float* s_part = sm + H1_OFF;

    const int tid  = threadIdx.x;
    const int warp = tid >> 5, lane = tid & 31;
    const int p    = blockIdx.y;
    const int b0   = blockIdx.x * TB;

    // ---------------- stage 0 ----------------
    for (int g = tid; g < TB * (OBSD / 4); g += THREADS) {
        int r = g / 12, q = g - r * 12;
        *(float4*)&s_obs[r * OBSD + q * 4] =
            *(const float4*)&obs[((size_t)(b0 + r) * NPLAYER + p) * OBSD + q * 4];
    }
    for (int g = tid; g < 768; g += THREADS) s_w3[g] = pi_W3[(size_t)p * 768 + g];
    if (tid < 3) s_w3[768 + tid] = pi_b3[p * 3 + tid];
    __syncthreads();

    // ---------------- stage 1a ----------------
    for (int i = tid; i < TB * 288; i += THREADS) {
        int r = i / 288, rest = i - r * 288, n = rest >> 5, j = rest & 31;
        const float* w = prop_W1 + ((p * 9 + n) * 2) * 32 + j;
        float h = s_obs[r * OBSD + 2 * n] * w[0]
                + s_obs[r * OBSD + 2 * n + 1] * w[32]
                + prop_b1[(p * 9 + n) * 32 + j];
        s_hid[r * PHID + n * 32 + j] = tf32f(lrelu(h));
    }
    for (int i = tid; i < TB * 64; i += THREADS) {
        int r = i >> 6, rest = i & 63, n = rest >> 5, j = rest & 31;
        const float* w = ext_W1 + ((p * 2 + n) * 6) * 32 + j;
        float h = ext_b1[(p * 2 + n) * 32 + j];
        #pragma unroll
        for (int q = 0; q < 6; q++) h += s_obs[r * OBSD + 18 + n * 6 + q] * w[q * 32];
        s_hid[r * PHID + 288 + n * 32 + j] = tf32f(lrelu(h));
    }
    for (int i = tid; i < TB * 32; i += THREADS) {
        int r = i >> 5, j = i & 31;
        const float* w = opp_W1 + (p * 18) * 32 + j;
        float h = opp_b1[p * 32 + j];
        #pragma unroll
        for (int q = 0; q < 18; q++) h += s_obs[r * OBSD + 30 + q] * w[q * 32];
        s_hid[r * PHID + 352 + j] = tf32f(lrelu(h));
    }
    __syncthreads();

    // ---------------- stage 1b ----------------
    enc_pass<64,  9, 0,   0, 0>(prop_b2, s_hid, s_enc, warp, lane, p);
    enc_pass<288, 2, 288, 1, 1>(ext_b2,  s_hid, s_enc, warp, lane, p);
    enc_pass<576, 1, 352, 2, 2>(opp_b2,  s_hid, s_enc, warp, lane, p);
    __syncthreads();

    // ---------------- stage 2 ----------------
    pi_stage<288, 36, PK_PI1, PENC, true>(pi_b1 + p * 256, s_enc,
                                          s_hid /*scratch*/, s_h1, PH1, warp, lane, p);
    __syncthreads();

    // ---------------- stage 3 ----------------
    pi_stage<128, 16, PK_PI2, PH1, false>(pi_b2 + p * 256, s_h1,
                                          s_enc /*scratch*/, s_hid /*h2*/, 256, warp, lane, p);
    __syncthreads();

    // ---------------- stage 4 ----------------
    if (tid < 384) {
        int q = tid & 3, a = (tid >> 2) % 3, r = tid / 12;
        float s = 0.f;
        const float* h2 = &s_hid[r * 256 + q * 64];
        const float* w3 = &s_w3[q * 64 * 3 + a];
        #pragma unroll 16
        for (int i = 0; i < 64; i++) s += h2[i] * w3[i * 3];
        s_part[tid] = s;
    }
    __syncthreads();
    if (tid < TB * 3) {
        int r = tid / 3, a = tid % 3;
        int base = (r * 3 + a) * 4;
        float s = s_w3[768 + a] + s_part[base] + s_part[base + 1]
                + s_part[base + 2] + s_part[base + 3];
        out[((size_t)(b0 + r) * NPLAYER + p) * 3 + a] = tanhf(s);
    }
}

extern "C" void kernel_launch(void* const* d_in, const int* in_sizes, int n_in,
                              void* d_out, int out_size)
{
    (void)in_sizes; (void)n_in; (void)out_size;
    const float* obs     = (const float*)d_in[0];
    const float* prop_W1 = (const float*)d_in[1];
    const float* prop_b1 = (const float*)d_in[2];
    const float* prop_W2 = (const float*)d_in[3];
    const float* prop_b2 = (const float*)d_in[4];
    const float* ext_W1  = (const float*)d_in[5];
    const float* ext_b1  = (const float*)d_in[6];
    const float* ext_W2  = (const float*)d_in[7];
    const float* ext_b2  = (const float*)d_in[8];
    const float* opp_W1  = (const float*)d_in[9];
    const float* opp_b1  = (const float*)d_in[10];
    const float* opp_W2  = (const float*)d_in[11];
    const float* opp_b2  = (const float*)d_in[12];
    const float* pi_W1   = (const float*)d_in[13];
    const float* pi_b1   = (const float*)d_in[14];
    const float* pi_W2   = (const float*)d_in[15];
    const float* pi_b2   = (const float*)d_in[16];
    const float* pi_W3   = (const float*)d_in[17];
    const float* pi_b3   = (const float*)d_in[18];
    float* out = (float*)d_out;

    repack_kernel<<<(PK_TOTAL + 255) / 256, 256>>>(prop_W2, ext_W2, opp_W2, pi_W1, pi_W2);

    const int smem_bytes = SMEM_FLOATS * sizeof(float);
    cudaFuncSetAttribute(mlpac_kernel, cudaFuncAttributeMaxDynamicSharedMemorySize, smem_bytes);

    dim3 grid(BATCH / TB, NPLAYER);
    mlpac_kernel<<<grid, THREADS, smem_bytes>>>(
        obs, prop_W1, prop_b1, prop_b2,
        ext_W1, ext_b1, ext_b2,
        opp_W1, opp_b1, opp_b2,
        pi_b1, pi_b2, pi_W3, pi_b3, out);
}

// round 8
// speedup vs baseline: 1.3265x; 1.3265x over previous
#include <cuda_runtime.h>

#define BATCH   65536
#define NPLAYER 3
#define OBSD    48
#define TB      32
#define THREADS 512

// pitches (floats)
#define PHID 388
#define PENC 580
#define PH1  260

// smem float offsets
#define HID_OFF 0
#define ENC_OFF 12416
#define H1_OFF  (ENC_OFF + 18560)
#define W3_OFF  (H1_OFF + 8320)
#define SMEM_FLOATS (W3_OFF + 772)

// packed weight buffer: per player 67072 float4s
//   enc (3 passes x 4608) : [0, 13824)
//   pi1 (16w x 36c x 2jp x 32) : [13824, 50688)
//   pi2 (16w x 16c x 2jp x 32) : [50688, 67072)
#define PK_PLAYER 67072
#define PK_TOTAL  (3 * PK_PLAYER)
#define PK_PI1    13824
#define PK_PI2    50688

__device__ float4 g_pk4[PK_TOTAL];

__device__ __forceinline__ float lrelu(float x) { return fmaxf(x, 0.01f * x); }

__device__ __forceinline__ unsigned f2tf(float x) {
    unsigned r;
    asm("cvt.rna.tf32.f32 %0, %1;" : "=r"(r) : "f"(x));
    return r;
}
__device__ __forceinline__ float tf32f(float x) { return __uint_as_float(f2tf(x)); }

__device__ __forceinline__ void mma_tf32(float d[4], unsigned a0, unsigned a1,
                                         unsigned a2, unsigned a3,
                                         unsigned b0, unsigned b1) {
    asm volatile(
        "mma.sync.aligned.m16n8k8.row.col.f32.tf32.tf32.f32 "
        "{%0,%1,%2,%3}, {%4,%5,%6,%7}, {%8,%9}, {%0,%1,%2,%3};"
        : "+f"(d[0]), "+f"(d[1]), "+f"(d[2]), "+f"(d[3])
        : "r"(a0), "r"(a1), "r"(a2), "r"(a3), "r"(b0), "r"(b1));
}

// =================== repack kernel (same layout as R7) ===================
__global__ void repack_kernel(const float* __restrict__ prop_W2,
                              const float* __restrict__ ext_W2,
                              const float* __restrict__ opp_W2,
                              const float* __restrict__ pi_W1,
                              const float* __restrict__ pi_W2) {
    int idx = blockIdx.x * 256 + threadIdx.x;
    if (idx >= PK_TOTAL) return;
    int p = idx / PK_PLAYER;
    int r = idx - p * PK_PLAYER;
    float o[4];
    if (r < PK_PI1) {
        int pp = r / 4608, e = r - pp * 4608;
        int warp = e / 384, rem = e - warp * 384;
        int tp = rem >> 7, rem2 = rem & 127;
        int k8 = rem2 >> 5, lane = rem2 & 31;
        int gr = lane >> 2, gc = lane & 3;
        #pragma unroll
        for (int q = 0; q < 4; q++) {
            int t = tp * 2 + (q >> 1), b = q & 1;
            int c0 = warp * 48 + t * 8;
            int k = k8 * 8 + gc + b * 4;
            float s;
            if (pp == 0) {
                int head = c0 >> 6;
                s = prop_W2[((size_t)(p * 9 + head) * 32 + k) * 64 + (c0 & 63) + gr];
            } else if (pp == 1) {
                int head = (c0 >= 288) ? 1 : 0;
                s = ext_W2[((size_t)(p * 2 + head) * 32 + k) * 288 + c0 - head * 288 + gr];
            } else {
                s = opp_W2[((size_t)p * 32 + k) * 576 + c0 + gr];
            }
            o[q] = tf32f(s);
        }
    } else if (r < PK_PI2) {
        int e = r - PK_PI1;
        int w = e / 2304, rem = e - w * 2304;
        int c = rem >> 6, rem2 = rem & 63;
        int jp = rem2 >> 5, lane = rem2 & 31;
        int h = w >> 3, nw = w & 7, gr = lane >> 2, gc = lane & 3;
        #pragma unroll
        for (int q = 0; q < 4; q++) {
            int j = jp * 2 + (q >> 1), b = q & 1;
            int k = h * 288 + c * 8 + gc + b * 4;
            int n = nw * 32 + j * 8 + gr;
            o[q] = tf32f(pi_W1[(size_t)p * 147456 + k * 256 + n]);
        }
    } else {
        int e = r - PK_PI2;
        int w = e >> 10, rem = e & 1023;
        int c = rem >> 6, rem2 = rem & 63;
        int jp = rem2 >> 5, lane = rem2 & 31;
        int h = w >> 3, nw = w & 7, gr = lane >> 2, gc = lane & 3;
        #pragma unroll
        for (int q = 0; q < 4; q++) {
            int j = jp * 2 + (q >> 1), b = q & 1;
            int k = h * 128 + c * 8 + gc + b * 4;
            int n = nw * 32 + j * 8 + gr;
            o[q] = tf32f(pi_W2[(size_t)p * 65536 + k * 256 + n]);
        }
    }
    g_pk4[idx] = make_float4(o[0], o[1], o[2], o[3]);
}

// =================== stage-1b pass: packed B, reg-prefetched, no syncs ===================
template<int HC, int NH, int ABASE, int MODE, int PPIDX>
__device__ __forceinline__ void enc_pass(const float* __restrict__ bias,
                                         const float* s_hid, float* s_enc,
                                         int warp, int lane, int p) {
    if (warp >= 12) return;
    const int gr = lane >> 2, gc = lane & 3;
    const int cw = warp * 48;
    const float4* pk = g_pk4 + (size_t)p * PK_PLAYER + PPIDX * 4608 + warp * 384 + lane;

    int headA[6];
    #pragma unroll
    for (int t = 0; t < 6; t++) {
        int c0 = cw + t * 8;
        headA[t] = (HC == 576) ? 0 : ((HC == 64) ? (c0 >> 6) : (c0 >= 288 ? 1 : 0));
    }

    float acc[6][2][4];
    #pragma unroll
    for (int t = 0; t < 6; t++)
        #pragma unroll
        for (int m = 0; m < 2; m++)
            #pragma unroll
            for (int u = 0; u < 4; u++) acc[t][m][u] = 0.f;

    float4 bv[3];
    #pragma unroll
    for (int tp = 0; tp < 3; tp++) bv[tp] = pk[tp * 4 * 32];

    #pragma unroll
    for (int k8 = 0; k8 < 4; k8++) {
        float4 nbv[3];
        if (k8 < 3) {
            #pragma unroll
            for (int tp = 0; tp < 3; tp++) nbv[tp] = pk[(tp * 4 + k8 + 1) * 32];
        }
        int cur = -1;
        unsigned a[2][4];
        #pragma unroll
        for (int t = 0; t < 6; t++) {
            if (headA[t] != cur) {
                cur = headA[t];
                int ac = ABASE + cur * 32 + k8 * 8 + gc;
                #pragma unroll
                for (int m = 0; m < 2; m++) {
                    int r = m * 16 + gr;
                    a[m][0] = __float_as_uint(s_hid[(r    ) * PHID + ac    ]);
                    a[m][1] = __float_as_uint(s_hid[(r + 8) * PHID + ac    ]);
                    a[m][2] = __float_as_uint(s_hid[(r    ) * PHID + ac + 4]);
                    a[m][3] = __float_as_uint(s_hid[(r + 8) * PHID + ac + 4]);
                }
            }
            unsigned b0 = __float_as_uint((t & 1) ? bv[t >> 1].z : bv[t >> 1].x);
            unsigned b1 = __float_as_uint((t & 1) ? bv[t >> 1].w : bv[t >> 1].y);
            mma_tf32(acc[t][0], a[0][0], a[0][1], a[0][2], a[0][3], b0, b1);
            mma_tf32(acc[t][1], a[1][0], a[1][1], a[1][2], a[1][3], b0, b1);
        }
        if (k8 < 3) {
            #pragma unroll
            for (int tp = 0; tp < 3; tp++) bv[tp] = nbv[tp];
        }
    }

    #pragma unroll
    for (int t = 0; t < 6; t++) {
        int cb = cw + t * 8 + 2 * gc;
        int head = headA[t];
        int cc = cb - head * HC;
        float b0 = bias[(p * NH + head) * HC + cc];
        float b1 = bias[(p * NH + head) * HC + cc + 1];
        #pragma unroll
        for (int m = 0; m < 2; m++) {
            int r = m * 16 + gr;
            float v00 = lrelu(acc[t][m][0] + b0), v01 = lrelu(acc[t][m][1] + b1);
            float v10 = lrelu(acc[t][m][2] + b0), v11 = lrelu(acc[t][m][3] + b1);
            float* e0 = &s_enc[(r    ) * PENC + cb];
            float* e1 = &s_enc[(r + 8) * PENC + cb];
            if (MODE == 0)      { e0[0] = v00; e0[1] = v01; e1[0] = v10; e1[1] = v11; }
            else if (MODE == 1) { e0[0] += v00; e0[1] += v01; e1[0] += v10; e1[1] += v11; }
            else {
                e0[0] = tf32f(e0[0] + v00); e0[1] = tf32f(e0[1] + v01);
                e1[0] = tf32f(e1[0] + v10); e1[1] = tf32f(e1[1] + v11);
            }
        }
    }
}

// =================== pi-head GEMM: M-split, full-K per warp, depth-2 B prefetch ===================
// 16 warps = 8 n-blocks x 2 m-groups; warp tile m16 x n32 over NCTOT 8-k chunks.
template<int NCTOT, int NCBLK, int PKOFF, int PA, bool OUT_TF32>
__device__ __forceinline__ void pi_stage(const float* __restrict__ bias,
                                         const float* sA,
                                         float* outp, int outPitch,
                                         int warp, int lane, int p) {
    const int h = warp >> 3, nw = warp & 7, n0 = nw * 32;
    const int gr = lane >> 2, gc = lane & 3;
    const int mbase = h * 16;
    const float4* pkb = g_pk4 + (size_t)p * PK_PLAYER + PKOFF;

    // chunk c -> float4 pair at ((blk*8+nw)*NCBLK + cc)*64 + {0,32} + lane
    auto pkaddr = [&](int c) -> const float4* {
        int blk = (c >= NCBLK) ? 1 : 0;
        int cc = c - blk * NCBLK;
        return pkb + ((size_t)(blk * 8 + nw) * NCBLK + cc) * 64 + lane;
    };

    float acc[4][4];
    #pragma unroll
    for (int j = 0; j < 4; j++)
        #pragma unroll
        for (int u = 0; u < 4; u++) acc[j][u] = 0.f;

    float4 b0r[2], b1r[2];
    {
        const float4* a0 = pkaddr(0); b0r[0] = a0[0]; b1r[0] = a0[32];
        const float4* a1 = pkaddr(1); b0r[1] = a1[0]; b1r[1] = a1[32];
    }

    #pragma unroll 4
    for (int c = 0; c < NCTOT; c++) {
        float4 v0 = b0r[c & 1], v1 = b1r[c & 1];
        if (c + 2 < NCTOT) {
            const float4* nx = pkaddr(c + 2);
            b0r[c & 1] = nx[0]; b1r[c & 1] = nx[32];
        }
        const int kg = c * 8 + gc;
        unsigned a0 = __float_as_uint(sA[(mbase + gr    ) * PA + kg    ]);
        unsigned a1 = __float_as_uint(sA[(mbase + gr + 8) * PA + kg    ]);
        unsigned a2 = __float_as_uint(sA[(mbase + gr    ) * PA + kg + 4]);
        unsigned a3 = __float_as_uint(sA[(mbase + gr + 8) * PA + kg + 4]);
        mma_tf32(acc[0], a0, a1, a2, a3, __float_as_uint(v0.x), __float_as_uint(v0.y));
        mma_tf32(acc[1], a0, a1, a2, a3, __float_as_uint(v0.z), __float_as_uint(v0.w));
        mma_tf32(acc[2], a0, a1, a2, a3, __float_as_uint(v1.x), __float_as_uint(v1.y));
        mma_tf32(acc[3], a0, a1, a2, a3, __float_as_uint(v1.z), __float_as_uint(v1.w));
    }

    // epilogue: warp-private m16 x n32 tile
    #pragma unroll
    for (int j = 0; j < 4; j++) {
        int cA = n0 + j * 8 + 2 * gc;
        float bb0 = bias[cA], bb1 = bias[cA + 1];
        float v00 = lrelu(acc[j][0] + bb0), v01 = lrelu(acc[j][1] + bb1);
        float v10 = lrelu(acc[j][2] + bb0), v11 = lrelu(acc[j][3] + bb1);
        if (OUT_TF32) { v00 = tf32f(v00); v01 = tf32f(v01); v10 = tf32f(v10); v11 = tf32f(v11); }
        outp[(mbase + gr    ) * outPitch + cA    ] = v00;
        outp[(mbase + gr    ) * outPitch + cA + 1] = v01;
        outp[(mbase + gr + 8) * outPitch + cA    ] = v10;
        outp[(mbase + gr + 8) * outPitch + cA + 1] = v11;
    }
}

__global__ __launch_bounds__(THREADS, 1)
void mlpac_kernel(
    const float* __restrict__ obs,
    const float* __restrict__ prop_W1, const float* __restrict__ prop_b1,
    const float* __restrict__ prop_b2,
    const float* __restrict__ ext_W1,  const float* __restrict__ ext_b1,
    const float* __restrict__ ext_b2,
    const float* __restrict__ opp_W1,  const float* __restrict__ opp_b1,
    const float* __restrict__ opp_b2,
    const float* __restrict__ pi_b1,   const float* __restrict__ pi_b2,
    const float* __restrict__ pi_W3,   const float* __restrict__ pi_b3,
    float* __restrict__ out)
{
    extern __shared__ float sm[];
    float* s_hid  = sm + HID_OFF;
    float* s_enc  = sm + ENC_OFF;
    float* s_h1   = sm + H1_OFF;
    float* s_obs  = s_enc;
    float* s_w3   = sm + W3_OFF;
    float* s_part = sm + H1_OFF;

    const int tid  = threadIdx.x;
    const int warp = tid >> 5, lane = tid & 31;
    const int p    = blockIdx.y;
    const int b0   = blockIdx.x * TB;

    // ---------------- stage 0 ----------------
    for (int g = tid; g < TB * (OBSD / 4); g += THREADS) {
        int r = g / 12, q = g - r * 12;
        *(float4*)&s_obs[r * OBSD + q * 4] =
            *(const float4*)&obs[((size_t)(b0 + r) * NPLAYER + p) * OBSD + q * 4];
    }
    for (int g = tid; g < 768; g += THREADS) s_w3[g] = pi_W3[(size_t)p * 768 + g];
    if (tid < 3) s_w3[768 + tid] = pi_b3[p * 3 + tid];
    __syncthreads();

    // ---------------- stage 1a ----------------
    for (int i = tid; i < TB * 288; i += THREADS) {
        int r = i / 288, rest = i - r * 288, n = rest >> 5, j = rest & 31;
        const float* w = prop_W1 + ((p * 9 + n) * 2) * 32 + j;
        float h = s_obs[r * OBSD + 2 * n] * w[0]
                + s_obs[r * OBSD + 2 * n + 1] * w[32]
                + prop_b1[(p * 9 + n) * 32 + j];
        s_hid[r * PHID + n * 32 + j] = tf32f(lrelu(h));
    }
    for (int i = tid; i < TB * 64; i += THREADS) {
        int r = i >> 6, rest = i & 63, n = rest >> 5, j = rest & 31;
        const float* w = ext_W1 + ((p * 2 + n) * 6) * 32 + j;
        float h = ext_b1[(p * 2 + n) * 32 + j];
        #pragma unroll
        for (int q = 0; q < 6; q++) h += s_obs[r * OBSD + 18 + n * 6 + q] * w[q * 32];
        s_hid[r * PHID + 288 + n * 32 + j] = tf32f(lrelu(h));
    }
    for (int i = tid; i < TB * 32; i += THREADS) {
        int r = i >> 5, j = i & 31;
        const float* w = opp_W1 + (p * 18) * 32 + j;
        float h = opp_b1[p * 32 + j];
        #pragma unroll
        for (int q = 0; q < 18; q++) h += s_obs[r * OBSD + 30 + q] * w[q * 32];
        s_hid[r * PHID + 352 + j] = tf32f(lrelu(h));
    }
    __syncthreads();

    // ---------------- stage 1b ----------------
    enc_pass<64,  9, 0,   0, 0>(prop_b2, s_hid, s_enc, warp, lane, p);
    enc_pass<288, 2, 288, 1, 1>(ext_b2,  s_hid, s_enc, warp, lane, p);
    enc_pass<576, 1, 352, 2, 2>(opp_b2,  s_hid, s_enc, warp, lane, p);
    __syncthreads();

    // ---------------- stage 2: h1 = lrelu(enc @ pi_W1 + b1) ----------------
    pi_stage<72, 36, PK_PI1, PENC, true>(pi_b1 + p * 256, s_enc, s_h1, PH1,
                                         warp, lane, p);
    __syncthreads();

    // ---------------- stage 3: h2 = lrelu(h1 @ pi_W2 + b2) ----------------
    pi_stage<32, 16, PK_PI2, PH1, false>(pi_b2 + p * 256, s_h1, s_hid /*h2*/, 256,
                                         warp, lane, p);
    __syncthreads();

    // ---------------- stage 4 ----------------
    if (tid < 384) {
        int q = tid & 3, a = (tid >> 2) % 3, r = tid / 12;
        float s = 0.f;
        const float* h2 = &s_hid[r * 256 + q * 64];
        const float* w3 = &s_w3[q * 64 * 3 + a];
        #pragma unroll 16
        for (int i = 0; i < 64; i++) s += h2[i] * w3[i * 3];
        s_part[tid] = s;
    }
    __syncthreads();
    if (tid < TB * 3) {
        int r = tid / 3, a = tid % 3;
        int base = (r * 3 + a) * 4;
        float s = s_w3[768 + a] + s_part[base] + s_part[base + 1]
                + s_part[base + 2] + s_part[base + 3];
        out[((size_t)(b0 + r) * NPLAYER + p) * 3 + a] = tanhf(s);
    }
}

extern "C" void kernel_launch(void* const* d_in, const int* in_sizes, int n_in,
                              void* d_out, int out_size)
{
    (void)in_sizes; (void)n_in; (void)out_size;
    const float* obs     = (const float*)d_in[0];
    const float* prop_W1 = (const float*)d_in[1];
    const float* prop_b1 = (const float*)d_in[2];
    const float* prop_W2 = (const float*)d_in[3];
    const float* prop_b2 = (const float*)d_in[4];
    const float* ext_W1  = (const float*)d_in[5];
    const float* ext_b1  = (const float*)d_in[6];
    const float* ext_W2  = (const float*)d_in[7];
    const float* ext_b2  = (const float*)d_in[8];
    const float* opp_W1  = (const float*)d_in[9];
    const float* opp_b1  = (const float*)d_in[10];
    const float* opp_W2  = (const float*)d_in[11];
    const float* opp_b2  = (const float*)d_in[12];
    const float* pi_W1   = (const float*)d_in[13];
    const float* pi_b1   = (const float*)d_in[14];
    const float* pi_W2   = (const float*)d_in[15];
    const float* pi_b2   = (const float*)d_in[16];
    const float* pi_W3   = (const float*)d_in[17];
    const float* pi_b3   = (const float*)d_in[18];
    float* out = (float*)d_out;

    repack_kernel<<<(PK_TOTAL + 255) / 256, 256>>>(prop_W2, ext_W2, opp_W2, pi_W1, pi_W2);

    const int smem_bytes = SMEM_FLOATS * sizeof(float);
    cudaFuncSetAttribute(mlpac_kernel, cudaFuncAttributeMaxDynamicSharedMemorySize, smem_bytes);

    dim3 grid(BATCH / TB, NPLAYER);
    mlpac_kernel<<<grid, THREADS, smem_bytes>>>(
        obs, prop_W1, prop_b1, prop_b2,
        ext_W1, ext_b1, ext_b2,
        opp_W1, opp_b1, opp_b2,
        pi_b1, pi_b2, pi_W3, pi_b3, out);
}

// round 9
// speedup vs baseline: 1.4904x; 1.1235x over previous
#include <cuda_runtime.h>

#define BATCH   65536
#define NPLAYER 3
#define OBSD    48
#define TB      32
#define THREADS 512

// pitches (floats)
#define PHID 388
#define PENC 580
#define PH1  260
#define PSCR 260

// smem float offsets
#define HID_OFF 0
#define ENC_OFF 12416
#define H1_OFF  (ENC_OFF + 18560)
#define W3_OFF  (H1_OFF + 8320)
#define SMEM_FLOATS (W3_OFF + 772)

// packed weight buffer: per player 67072 float4s
//   enc (3 passes x 4608)                      : [0, 13824)
//   pi1 (2h x 36c x 8nw x 2jp x 32 lanes)      : [13824, 50688)
//   pi2 (2h x 16c x 8nw x 2jp x 32 lanes)      : [50688, 67072)
#define PK_PLAYER 67072
#define PK_TOTAL  (3 * PK_PLAYER)
#define PK_PI1    13824
#define PK_PI2    50688

__device__ float4 g_pk4[PK_TOTAL];

__device__ __forceinline__ float lrelu(float x) { return fmaxf(x, 0.01f * x); }

__device__ __forceinline__ unsigned f2tf(float x) {
    unsigned r;
    asm("cvt.rna.tf32.f32 %0, %1;" : "=r"(r) : "f"(x));
    return r;
}
__device__ __forceinline__ float tf32f(float x) { return __uint_as_float(f2tf(x)); }

__device__ __forceinline__ void mma_tf32(float d[4], unsigned a0, unsigned a1,
                                         unsigned a2, unsigned a3,
                                         unsigned b0, unsigned b1) {
    asm volatile(
        "mma.sync.aligned.m16n8k8.row.col.f32.tf32.tf32.f32 "
        "{%0,%1,%2,%3}, {%4,%5,%6,%7}, {%8,%9}, {%0,%1,%2,%3};"
        : "+f"(d[0]), "+f"(d[1]), "+f"(d[2]), "+f"(d[3])
        : "r"(a0), "r"(a1), "r"(a2), "r"(a3), "r"(b0), "r"(b1));
}

// =================== repack kernel ===================
__global__ void repack_kernel(const float* __restrict__ prop_W2,
                              const float* __restrict__ ext_W2,
                              const float* __restrict__ opp_W2,
                              const float* __restrict__ pi_W1,
                              const float* __restrict__ pi_W2) {
    int idx = blockIdx.x * 256 + threadIdx.x;
    if (idx >= PK_TOTAL) return;
    int p = idx / PK_PLAYER;
    int r = idx - p * PK_PLAYER;
    float o[4];
    if (r < PK_PI1) {
        // enc packed: pass pp, (((warp*3+tp)*4+k8)*32+lane)
        int pp = r / 4608, e = r - pp * 4608;
        int warp = e / 384, rem = e - warp * 384;
        int tp = rem >> 7, rem2 = rem & 127;
        int k8 = rem2 >> 5, lane = rem2 & 31;
        int gr = lane >> 2, gc = lane & 3;
        #pragma unroll
        for (int q = 0; q < 4; q++) {
            int t = tp * 2 + (q >> 1), b = q & 1;
            int c0 = warp * 48 + t * 8;
            int k = k8 * 8 + gc + b * 4;
            float s;
            if (pp == 0) {
                int head = c0 >> 6;
                s = prop_W2[((size_t)(p * 9 + head) * 32 + k) * 64 + (c0 & 63) + gr];
            } else if (pp == 1) {
                int head = (c0 >= 288) ? 1 : 0;
                s = ext_W2[((size_t)(p * 2 + head) * 32 + k) * 288 + c0 - head * 288 + gr];
            } else {
                s = opp_W2[((size_t)p * 32 + k) * 576 + c0 + gr];
            }
            o[q] = tf32f(s);
        }
    } else if (r < PK_PI2) {
        // pi1: (((h*36 + c)*8 + nw)*2 + jp)*32 + lane
        int e = r - PK_PI1;
        int lane = e & 31, t1 = e >> 5;
        int jp = t1 & 1, t2 = t1 >> 1;
        int nw = t2 & 7, t3 = t2 >> 3;
        int c = t3 % 36, h = t3 / 36;
        int gr = lane >> 2, gc = lane & 3;
        #pragma unroll
        for (int q = 0; q < 4; q++) {
            int j = jp * 2 + (q >> 1), b = q & 1;
            int k = h * 288 + c * 8 + gc + b * 4;
            int n = nw * 32 + j * 8 + gr;
            o[q] = tf32f(pi_W1[(size_t)p * 147456 + k * 256 + n]);
        }
    } else {
        // pi2: (((h*16 + c)*8 + nw)*2 + jp)*32 + lane
        int e = r - PK_PI2;
        int lane = e & 31, t1 = e >> 5;
        int jp = t1 & 1, t2 = t1 >> 1;
        int nw = t2 & 7, t3 = t2 >> 3;
        int c = t3 & 15, h = t3 >> 4;
        int gr = lane >> 2, gc = lane & 3;
        #pragma unroll
        for (int q = 0; q < 4; q++) {
            int j = jp * 2 + (q >> 1), b = q & 1;
            int k = h * 128 + c * 8 + gc + b * 4;
            int n = nw * 32 + j * 8 + gr;
            o[q] = tf32f(pi_W2[(size_t)p * 65536 + k * 256 + n]);
        }
    }
    g_pk4[idx] = make_float4(o[0], o[1], o[2], o[3]);
}

// =================== stage-1b pass (as R8) ===================
template<int HC, int NH, int ABASE, int MODE, int PPIDX>
__device__ __forceinline__ void enc_pass(const float* __restrict__ bias,
                                         const float* s_hid, float* s_enc,
                                         int warp, int lane, int p) {
    if (warp >= 12) return;
    const int gr = lane >> 2, gc = lane & 3;
    const int cw = warp * 48;
    const float4* pk = g_pk4 + (size_t)p * PK_PLAYER + PPIDX * 4608 + warp * 384 + lane;

    int headA[6];
    #pragma unroll
    for (int t = 0; t < 6; t++) {
        int c0 = cw + t * 8;
        headA[t] = (HC == 576) ? 0 : ((HC == 64) ? (c0 >> 6) : (c0 >= 288 ? 1 : 0));
    }

    float acc[6][2][4];
    #pragma unroll
    for (int t = 0; t < 6; t++)
        #pragma unroll
        for (int m = 0; m < 2; m++)
            #pragma unroll
            for (int u = 0; u < 4; u++) acc[t][m][u] = 0.f;

    float4 bv[3];
    #pragma unroll
    for (int tp = 0; tp < 3; tp++) bv[tp] = pk[tp * 4 * 32];

    #pragma unroll
    for (int k8 = 0; k8 < 4; k8++) {
        float4 nbv[3];
        if (k8 < 3) {
            #pragma unroll
            for (int tp = 0; tp < 3; tp++) nbv[tp] = pk[(tp * 4 + k8 + 1) * 32];
        }
        int cur = -1;
        unsigned a[2][4];
        #pragma unroll
        for (int t = 0; t < 6; t++) {
            if (headA[t] != cur) {
                cur = headA[t];
                int ac = ABASE + cur * 32 + k8 * 8 + gc;
                #pragma unroll
                for (int m = 0; m < 2; m++) {
                    int r = m * 16 + gr;
                    a[m][0] = __float_as_uint(s_hid[(r    ) * PHID + ac    ]);
                    a[m][1] = __float_as_uint(s_hid[(r + 8) * PHID + ac    ]);
                    a[m][2] = __float_as_uint(s_hid[(r    ) * PHID + ac + 4]);
                    a[m][3] = __float_as_uint(s_hid[(r + 8) * PHID + ac + 4]);
                }
            }
            unsigned b0 = __float_as_uint((t & 1) ? bv[t >> 1].z : bv[t >> 1].x);
            unsigned b1 = __float_as_uint((t & 1) ? bv[t >> 1].w : bv[t >> 1].y);
            mma_tf32(acc[t][0], a[0][0], a[0][1], a[0][2], a[0][3], b0, b1);
            mma_tf32(acc[t][1], a[1][0], a[1][1], a[1][2], a[1][3], b0, b1);
        }
        if (k8 < 3) {
            #pragma unroll
            for (int tp = 0; tp < 3; tp++) bv[tp] = nbv[tp];
        }
    }

    #pragma unroll
    for (int t = 0; t < 6; t++) {
        int cb = cw + t * 8 + 2 * gc;
        int head = headA[t];
        int cc = cb - head * HC;
        float b0 = bias[(p * NH + head) * HC + cc];
        float b1 = bias[(p * NH + head) * HC + cc + 1];
        #pragma unroll
        for (int m = 0; m < 2; m++) {
            int r = m * 16 + gr;
            float v00 = lrelu(acc[t][m][0] + b0), v01 = lrelu(acc[t][m][1] + b1);
            float v10 = lrelu(acc[t][m][2] + b0), v11 = lrelu(acc[t][m][3] + b1);
            float* e0 = &s_enc[(r    ) * PENC + cb];
            float* e1 = &s_enc[(r + 8) * PENC + cb];
            if (MODE == 0)      { e0[0] = v00; e0[1] = v01; e1[0] = v10; e1[1] = v11; }
            else if (MODE == 1) { e0[0] += v00; e0[1] += v01; e1[0] += v10; e1[1] += v11; }
            else {
                e0[0] = tf32f(e0[0] + v00); e0[1] = tf32f(e0[1] + v01);
                e1[0] = tf32f(e1[0] + v10); e1[1] = tf32f(e1[1] + v11);
            }
        }
    }
}

// =================== pi-head GEMM: K-split m32n32, linear packed B, depth-2 prefetch ===================
template<int KHALF, int NCH, int PKOFF, int PA, bool OUT_TF32>
__device__ __forceinline__ void pi_stage(const float* __restrict__ bias,
                                         const float* sA, float* scr,
                                         float* outp, int outPitch,
                                         int warp, int lane, int p) {
    const int h = warp >> 3, nw = warp & 7, n0 = nw * 32;
    const int gr = lane >> 2, gc = lane & 3;
    const float4* pk = g_pk4 + (size_t)p * PK_PLAYER + PKOFF
                     + ((size_t)h * NCH * 8 + nw) * 64 + lane;
    const int kbase = h * KHALF + gc;

    float acc[2][4][4];
    #pragma unroll
    for (int m = 0; m < 2; m++)
        #pragma unroll
        for (int j = 0; j < 4; j++)
            #pragma unroll
            for (int u = 0; u < 4; u++) acc[m][j][u] = 0.f;

    float4 b0r[2], b1r[2];
    b0r[0] = pk[0];   b1r[0] = pk[32];
    b0r[1] = pk[512]; b1r[1] = pk[512 + 32];

    #pragma unroll 4
    for (int c = 0; c < NCH; c++) {
        float4 v0 = b0r[c & 1], v1 = b1r[c & 1];
        if (c + 2 < NCH) {
            b0r[c & 1] = pk[(c + 2) * 512];
            b1r[c & 1] = pk[(c + 2) * 512 + 32];
        }
        const int kg = kbase + c * 8;
        unsigned a[2][4];
        #pragma unroll
        for (int m = 0; m < 2; m++) {
            int r = m * 16 + gr;
            a[m][0] = __float_as_uint(sA[(r    ) * PA + kg    ]);
            a[m][1] = __float_as_uint(sA[(r + 8) * PA + kg    ]);
            a[m][2] = __float_as_uint(sA[(r    ) * PA + kg + 4]);
            a[m][3] = __float_as_uint(sA[(r + 8) * PA + kg + 4]);
        }
        #pragma unroll
        for (int m = 0; m < 2; m++) {
            mma_tf32(acc[m][0], a[m][0], a[m][1], a[m][2], a[m][3],
                     __float_as_uint(v0.x), __float_as_uint(v0.y));
            mma_tf32(acc[m][1], a[m][0], a[m][1], a[m][2], a[m][3],
                     __float_as_uint(v0.z), __float_as_uint(v0.w));
            mma_tf32(acc[m][2], a[m][0], a[m][1], a[m][2], a[m][3],
                     __float_as_uint(v1.x), __float_as_uint(v1.y));
            mma_tf32(acc[m][3], a[m][0], a[m][1], a[m][2], a[m][3],
                     __float_as_uint(v1.z), __float_as_uint(v1.w));
        }
    }

    // K-split reduction: half1 stores raw partials, half0 finalizes
    if (h == 1) {
        #pragma unroll
        for (int m = 0; m < 2; m++) {
            int r = m * 16 + gr;
            #pragma unroll
            for (int j = 0; j < 4; j++) {
                int cA = n0 + j * 8 + 2 * gc;
                scr[(r    ) * PSCR + cA] = acc[m][j][0]; scr[(r    ) * PSCR + cA + 1] = acc[m][j][1];
                scr[(r + 8) * PSCR + cA] = acc[m][j][2]; scr[(r + 8) * PSCR + cA + 1] = acc[m][j][3];
            }
        }
    }
    __syncthreads();
    if (h == 0) {
        #pragma unroll
        for (int m = 0; m < 2; m++) {
            int r = m * 16 + gr;
            #pragma unroll
            for (int j = 0; j < 4; j++) {
                int cA = n0 + j * 8 + 2 * gc;
                float b0 = bias[cA], b1 = bias[cA + 1];
                float v00 = lrelu(acc[m][j][0] + scr[(r    ) * PSCR + cA    ] + b0);
                float v01 = lrelu(acc[m][j][1] + scr[(r    ) * PSCR + cA + 1] + b1);
                float v10 = lrelu(acc[m][j][2] + scr[(r + 8) * PSCR + cA    ] + b0);
                float v11 = lrelu(acc[m][j][3] + scr[(r + 8) * PSCR + cA + 1] + b1);
                if (OUT_TF32) { v00 = tf32f(v00); v01 = tf32f(v01); v10 = tf32f(v10); v11 = tf32f(v11); }
                outp[(r    ) * outPitch + cA    ] = v00;
                outp[(r    ) * outPitch + cA + 1] = v01;
                outp[(r + 8) * outPitch + cA    ] = v10;
                outp[(r + 8) * outPitch + cA + 1] = v11;
            }
        }
    }
}

__global__ __launch_bounds__(THREADS, 1)
void mlpac_kernel(
    const float* __restrict__ obs,
    const float* __restrict__ prop_W1, const float* __restrict__ prop_b1,
    const float* __restrict__ prop_b2,
    const float* __restrict__ ext_W1,  const float* __restrict__ ext_b1,
    const float* __restrict__ ext_b2,
    const float* __restrict__ opp_W1,  const float* __restrict__ opp_b1,
    const float* __restrict__ opp_b2,
    const float* __restrict__ pi_b1,   const float* __restrict__ pi_b2,
    const float* __restrict__ pi_W3,   const float* __restrict__ pi_b3,
    float* __restrict__ out)
{
    extern __shared__ float sm[];
    float* s_hid  = sm + HID_OFF;
    float* s_enc  = sm + ENC_OFF;
    float* s_h1   = sm + H1_OFF;
    float* s_obs  = s_enc;
    float* s_w3   = sm + W3_OFF;
    float* s_part = sm + H1_OFF;

    const int tid  = threadIdx.x;
    const int warp = tid >> 5, lane = tid & 31;
    const int p    = blockIdx.y;
    const int b0   = blockIdx.x * TB;

    // ---------------- stage 0 ----------------
    for (int g = tid; g < TB * (OBSD / 4); g += THREADS) {
        int r = g / 12, q = g - r * 12;
        *(float4*)&s_obs[r * OBSD + q * 4] =
            *(const float4*)&obs[((size_t)(b0 + r) * NPLAYER + p) * OBSD + q * 4];
    }
    for (int g = tid; g < 768; g += THREADS) s_w3[g] = pi_W3[(size_t)p * 768 + g];
    if (tid < 3) s_w3[768 + tid] = pi_b3[p * 3 + tid];
    __syncthreads();

    // ---------------- stage 1a ----------------
    for (int i = tid; i < TB * 288; i += THREADS) {
        int r = i / 288, rest = i - r * 288, n = rest >> 5, j = rest & 31;
        const float* w = prop_W1 + ((p * 9 + n) * 2) * 32 + j;
        float h = s_obs[r * OBSD + 2 * n] * w[0]
                + s_obs[r * OBSD + 2 * n + 1] * w[32]
                + prop_b1[(p * 9 + n) * 32 + j];
        s_hid[r * PHID + n * 32 + j] = tf32f(lrelu(h));
    }
    for (int i = tid; i < TB * 64; i += THREADS) {
        int r = i >> 6, rest = i & 63, n = rest >> 5, j = rest & 31;
        const float* w = ext_W1 + ((p * 2 + n) * 6) * 32 + j;
        float h = ext_b1[(p * 2 + n) * 32 + j];
        #pragma unroll
        for (int q = 0; q < 6; q++) h += s_obs[r * OBSD + 18 + n * 6 + q] * w[q * 32];
        s_hid[r * PHID + 288 + n * 32 + j] = tf32f(lrelu(h));
    }
    for (int i = tid; i < TB * 32; i += THREADS) {
        int r = i >> 5, j = i & 31;
        const float* w = opp_W1 + (p * 18) * 32 + j;
        float h = opp_b1[p * 32 + j];
        #pragma unroll
        for (int q = 0; q < 18; q++) h += s_obs[r * OBSD + 30 + q] * w[q * 32];
        s_hid[r * PHID + 352 + j] = tf32f(lrelu(h));
    }
    __syncthreads();

    // ---------------- stage 1b ----------------
    enc_pass<64,  9, 0,   0, 0>(prop_b2, s_hid, s_enc, warp, lane, p);
    enc_pass<288, 2, 288, 1, 1>(ext_b2,  s_hid, s_enc, warp, lane, p);
    enc_pass<576, 1, 352, 2, 2>(opp_b2,  s_hid, s_enc, warp, lane, p);
    __syncthreads();

    // ---------------- stage 2: h1 = lrelu(enc @ pi_W1 + b1) ----------------
    pi_stage<288, 36, PK_PI1, PENC, true>(pi_b1 + p * 256, s_enc,
                                          s_hid /*scratch*/, s_h1, PH1, warp, lane, p);
    __syncthreads();

    // ---------------- stage 3: h2 = lrelu(h1 @ pi_W2 + b2) ----------------
    pi_stage<128, 16, PK_PI2, PH1, false>(pi_b2 + p * 256, s_h1,
                                          s_enc /*scratch*/, s_hid /*h2*/, 256, warp, lane, p);
    __syncthreads();

    // ---------------- stage 4 ----------------
    if (tid < 384) {
        int q = tid & 3, a = (tid >> 2) % 3, r = tid / 12;
        float s = 0.f;
        const float* h2 = &s_hid[r * 256 + q * 64];
        const float* w3 = &s_w3[q * 64 * 3 + a];
        #pragma unroll 16
        for (int i = 0; i < 64; i++) s += h2[i] * w3[i * 3];
        s_part[tid] = s;
    }
    __syncthreads();
    if (tid < TB * 3) {
        int r = tid / 3, a = tid % 3;
        int base = (r * 3 + a) * 4;
        float s = s_w3[768 + a] + s_part[base] + s_part[base + 1]
                + s_part[base + 2] + s_part[base + 3];
        out[((size_t)(b0 + r) * NPLAYER + p) * 3 + a] = tanhf(s);
    }
}

extern "C" void kernel_launch(void* const* d_in, const int* in_sizes, int n_in,
                              void* d_out, int out_size)
{
    (void)in_sizes; (void)n_in; (void)out_size;
    const float* obs     = (const float*)d_in[0];
    const float* prop_W1 = (const float*)d_in[1];
    const float* prop_b1 = (const float*)d_in[2];
    const float* prop_W2 = (const float*)d_in[3];
    const float* prop_b2 = (const float*)d_in[4];
    const float* ext_W1  = (const float*)d_in[5];
    const float* ext_b1  = (const float*)d_in[6];
    const float* ext_W2  = (const float*)d_in[7];
    const float* ext_b2  = (const float*)d_in[8];
    const float* opp_W1  = (const float*)d_in[9];
    const float* opp_b1  = (const float*)d_in[10];
    const float* opp_W2  = (const float*)d_in[11];
    const float* opp_b2  = (const float*)d_in[12];
    const float* pi_W1   = (const float*)d_in[13];
    const float* pi_b1   = (const float*)d_in[14];
    const float* pi_W2   = (const float*)d_in[15];
    const float* pi_b2   = (const float*)d_in[16];
    const float* pi_W3   = (const float*)d_in[17];
    const float* pi_b3   = (const float*)d_in[18];
    float* out = (float*)d_out;

    repack_kernel<<<(PK_TOTAL + 255) / 256, 256>>>(prop_W2, ext_W2, opp_W2, pi_W1, pi_W2);

    const int smem_bytes = SMEM_FLOATS * sizeof(float);
    cudaFuncSetAttribute(mlpac_kernel, cudaFuncAttributeMaxDynamicSharedMemorySize, smem_bytes);

    dim3 grid(BATCH / TB, NPLAYER);
    mlpac_kernel<<<grid, THREADS, smem_bytes>>>(
        obs, prop_W1, prop_b1, prop_b2,
        ext_W1, ext_b1, ext_b2,
        opp_W1, opp_b1, opp_b2,
        pi_b1, pi_b2, pi_W3, pi_b3, out);
}